// round 12
// baseline (speedup 1.0000x reference)
#include <cuda_runtime.h>
#include <cstdint>
#include <math.h>

// Problem constants
#define LL 512
#define DD 128
#define HB 128          // H*B
#define MM 8192         // B*L
#define HD 1024
#define INV_SQRT_D 0.08838834764831843f

// Scratch (device globals; allocation is forbidden)
__device__ __align__(128) float g_Q[HB * LL * DD];
__device__ __align__(128) float g_K[HB * LL * DD];
__device__ __align__(128) float g_Vt[HB * DD * LL];    // V transposed: [n][d][l]
__device__ __align__(128) float g_S[HB * LL * LL];     // raw masked+scaled scores
__device__ __align__(128) float g_ATT[HB * LL * DD];   // flat view == (B,L,H*D)
// Query-axis softmax stats: partial per 128-q block, then combined
__device__ __align__(128) float g_pmax[4 * HB * LL];
__device__ __align__(128) float g_psum[4 * HB * LL];
__device__ __align__(128) float g_M[HB * LL];
__device__ __align__(128) float g_inv[HB * LL];

// ---------------------------------------------------------------------------
// Tiling: block 128x128, warps 4(m) x 2(n), warp tile 32x64, K chunk 32.
// 3-stage cp.async pipeline: A0..A2, B0..B2.
// ---------------------------------------------------------------------------
#define KC 32
#define ROWPAD 36
#define TILE_B (128 * ROWPAD * 4)      // 18432 bytes per tile buffer
#define SMEM_BYTES (6 * TILE_B)        // 110592

__device__ __forceinline__ uint32_t smem_u32(const void* p) {
    uint32_t a;
    asm("{ .reg .u64 t; cvta.to.shared.u64 t, %1; cvt.u32.u64 %0, t; }" : "=r"(a) : "l"(p));
    return a;
}
__device__ __forceinline__ void cp16(uint32_t saddr, const void* g) {
    asm volatile("cp.async.cg.shared.global [%0], [%1], 16;" :: "r"(saddr), "l"(g));
}
#define CP_COMMIT() asm volatile("cp.async.commit_group;" ::: "memory")
#define CP_WAIT(N)  asm volatile("cp.async.wait_group %0;" :: "n"(N) : "memory")

__device__ __forceinline__ uint32_t tf32_rna(float f) {
    uint32_t r;
    asm("cvt.rna.tf32.f32 %0, %1;" : "=r"(r) : "f"(f));
    return r;
}
__device__ __forceinline__ void split_tf32(float v, uint32_t& hi, uint32_t& lo) {
    hi = tf32_rna(v);
    lo = tf32_rna(v - __uint_as_float(hi));
}

__device__ __forceinline__ void mma8(float acc[4],
                                     uint32_t a0, uint32_t a1, uint32_t a2, uint32_t a3,
                                     uint32_t b0, uint32_t b1) {
    asm volatile(
        "mma.sync.aligned.m16n8k8.row.col.f32.tf32.tf32.f32 "
        "{%0,%1,%2,%3}, {%4,%5,%6,%7}, {%8,%9}, {%0,%1,%2,%3};"
        : "+f"(acc[0]), "+f"(acc[1]), "+f"(acc[2]), "+f"(acc[3])
        : "r"(a0), "r"(a1), "r"(a2), "r"(a3), "r"(b0), "r"(b1));
}

__device__ __forceinline__ void load_async(uint32_t sbase, const float* __restrict__ src,
                                           int ld, int tid) {
#pragma unroll
    for (int i = 0; i < 4; ++i) {
        int idx = tid + i * 256;
        int row = idx >> 3;
        int c4 = idx & 7;
        cp16(sbase + (row * ROWPAD + c4 * 4) * 4, src + row * ld + c4 * 4);
    }
}

// One K=32 chunk — 3xTF32 split precision. Scalar conflict-free smem reads
// (round-5 proven), but MMAs issued term-major across the mt pair so the
// RAW dependency distance on each accumulator is 2 instead of 1.
// EXP: A element -> exp(a - M[k]) * inv[k] before split (fused softmax apply).
template<bool EXP>
__device__ __forceinline__ void compute_chunk(const float (*As)[ROWPAD],
                                              const float (*Bs)[ROWPAD],
                                              int wm, int wn, int g, int t,
                                              const float* __restrict__ Mrow,
                                              const float* __restrict__ Irow,
                                              float acc[2][8][4]) {
#pragma unroll
    for (int ks = 0; ks < 4; ++ks) {
        int k = ks * 8;
        float M0 = 0.f, I0 = 0.f, M1 = 0.f, I1 = 0.f;
        if (EXP) {
            M0 = Mrow[k + t];     I0 = Irow[k + t];
            M1 = Mrow[k + t + 4]; I1 = Irow[k + t + 4];
        }
        uint32_t ah[2][4], al[2][4];
#pragma unroll
        for (int mt = 0; mt < 2; ++mt) {
            int r = wm * 32 + mt * 16;
            float a0 = As[r + g][k + t];
            float a1 = As[r + g + 8][k + t];
            float a2 = As[r + g][k + t + 4];
            float a3 = As[r + g + 8][k + t + 4];
            if (EXP) {
                a0 = __expf(a0 - M0) * I0;
                a1 = __expf(a1 - M0) * I0;
                a2 = __expf(a2 - M1) * I1;
                a3 = __expf(a3 - M1) * I1;
            }
            split_tf32(a0, ah[mt][0], al[mt][0]);
            split_tf32(a1, ah[mt][1], al[mt][1]);
            split_tf32(a2, ah[mt][2], al[mt][2]);
            split_tf32(a3, ah[mt][3], al[mt][3]);
        }
#pragma unroll
        for (int nt = 0; nt < 8; ++nt) {
            int c = wn * 64 + nt * 8;
            uint32_t bh0, bl0, bh1, bl1;
            split_tf32(Bs[c + g][k + t],     bh0, bl0);
            split_tf32(Bs[c + g][k + t + 4], bh1, bl1);
            // term-major across the mt pair: dep distance 2 on each acc
            mma8(acc[0][nt], ah[0][0], ah[0][1], ah[0][2], ah[0][3], bh0, bh1);
            mma8(acc[1][nt], ah[1][0], ah[1][1], ah[1][2], ah[1][3], bh0, bh1);
            mma8(acc[0][nt], ah[0][0], ah[0][1], ah[0][2], ah[0][3], bl0, bl1);
            mma8(acc[1][nt], ah[1][0], ah[1][1], ah[1][2], ah[1][3], bl0, bl1);
            mma8(acc[0][nt], al[0][0], al[0][1], al[0][2], al[0][3], bh0, bh1);
            mma8(acc[1][nt], al[1][0], al[1][1], al[1][2], al[1][3], bh0, bh1);
        }
    }
}

// Full main loop: nc K-chunks, 3-stage cp.async pipeline.
template<bool EXP>
__device__ __forceinline__ void gemm_main(char* sm, uint32_t smb,
                                          const float* __restrict__ A, int lda,
                                          const float* __restrict__ B, int ldb,
                                          int nc, int tid, int wm, int wn, int g, int t,
                                          const float* __restrict__ Mb,
                                          const float* __restrict__ Ib,
                                          float acc[2][8][4]) {
    // Prologue: prefetch chunks 0 and 1 (each A+B pair = one commit group).
    load_async(smb, A, lda, tid);
    load_async(smb + 3 * TILE_B, B, ldb, tid);
    CP_COMMIT();
    if (nc > 1) {
        load_async(smb + TILE_B, A + KC, lda, tid);
        load_async(smb + 4 * TILE_B, B + KC, ldb, tid);
        CP_COMMIT();
    }
#pragma unroll 1
    for (int c = 0; c < nc; ++c) {
        if (c + 2 < nc) {
            int nb = (c + 2) % 3;
            load_async(smb + nb * TILE_B, A + (c + 2) * KC, lda, tid);
            load_async(smb + (3 + nb) * TILE_B, B + (c + 2) * KC, ldb, tid);
            CP_COMMIT();
            CP_WAIT(2);            // group c retired; c+1, c+2 may remain
        } else if (c + 1 < nc) {
            CP_WAIT(1);
        } else {
            CP_WAIT(0);
        }
        __syncthreads();
        int cb = c % 3;
        compute_chunk<EXP>((const float(*)[ROWPAD])(sm + cb * TILE_B),
                           (const float(*)[ROWPAD])(sm + (3 + cb) * TILE_B),
                           wm, wn, g, t,
                           EXP ? Mb + c * KC : (const float*)nullptr,
                           EXP ? Ib + c * KC : (const float*)nullptr,
                           acc);
        __syncthreads();
    }
}

// ---------------------------------------------------------------------------
// K1: QKV projection. grid (8, 64, 3), block 256.
// ---------------------------------------------------------------------------
__global__ __launch_bounds__(256) void k_qkv(
    const float* __restrict__ x,
    const float* __restrict__ Wq, const float* __restrict__ bq,
    const float* __restrict__ Wk, const float* __restrict__ bk,
    const float* __restrict__ Wv, const float* __restrict__ bv) {
    extern __shared__ char sm[];
    uint32_t smb = smem_u32(sm);
    int tid = threadIdx.x, wid = tid >> 5, lane = tid & 31;
    int wm = wid & 3, wn = wid >> 2, g = lane >> 2, t = lane & 3;
    int sel = blockIdx.z;
    int e0 = blockIdx.x * 128;
    int m0 = blockIdx.y * 128;
    const float* W = (sel == 0) ? Wq : (sel == 1) ? Wk : Wv;
    const float* bias = (sel == 0) ? bq : (sel == 1) ? bk : bv;

    float acc[2][8][4] = {};
    gemm_main<false>(sm, smb, x + m0 * DD, DD, W + e0 * DD, DD, 4,
                     tid, wm, wn, g, t, nullptr, nullptr, acc);

    int h = e0 >> 7;
#pragma unroll
    for (int mt = 0; mt < 2; ++mt) {
#pragma unroll
        for (int nt = 0; nt < 8; ++nt) {
            int col = wn * 64 + nt * 8 + t * 2;
            float bi0 = bias[e0 + col], bi1 = bias[e0 + col + 1];
#pragma unroll
            for (int half = 0; half < 2; ++half) {
                int row = wm * 32 + mt * 16 + g + half * 8;
                int m = m0 + row;
                int b = m >> 9, l = m & 511;
                int n = (h << 4) + b;
                float v0 = acc[mt][nt][half * 2] + bi0;
                float v1 = acc[mt][nt][half * 2 + 1] + bi1;
                if (sel < 2) {
                    float* dst = ((sel == 0) ? g_Q : g_K) + (n * LL + l) * DD + col;
                    *(float2*)dst = make_float2(v0, v1);
                } else {
                    float* dst = g_Vt + n * (DD * LL) + l;
                    dst[col * LL] = v0;
                    dst[(col + 1) * LL] = v1;
                }
            }
        }
    }
}

// ---------------------------------------------------------------------------
// K2: scores + per-block column softmax partials. grid (4, 4, 128), block 256.
// ---------------------------------------------------------------------------
__global__ __launch_bounds__(256) void k_scores(const int* __restrict__ mask) {
    extern __shared__ char sm[];
    uint32_t smb = smem_u32(sm);
    int tid = threadIdx.x, wid = tid >> 5, lane = tid & 31;
    int wm = wid & 3, wn = wid >> 2, g = lane >> 2, t = lane & 3;
    int n = blockIdx.z;
    int kc0 = blockIdx.x * 128;
    int q0 = blockIdx.y * 128;

    float acc[2][8][4] = {};
    gemm_main<false>(sm, smb, g_Q + (n * LL + q0) * DD, DD,
                     g_K + (n * LL + kc0) * DD, DD, 4,
                     tid, wm, wn, g, t, nullptr, nullptr, acc);

    // Mask + scale into acc; store raw S.
    const int* mbase = mask + (n & 15) * (LL * LL);
    float* sbase = g_S + n * (LL * LL);
#pragma unroll
    for (int mt = 0; mt < 2; ++mt) {
#pragma unroll
        for (int nt = 0; nt < 8; ++nt) {
            int col = kc0 + wn * 64 + nt * 8 + t * 2;
#pragma unroll
            for (int half = 0; half < 2; ++half) {
                int q = q0 + wm * 32 + mt * 16 + g + half * 8;
                int2 mk = *(const int2*)(mbase + q * LL + col);
                float v0 = (mk.x ? -1e9f : acc[mt][nt][half * 2]) * INV_SQRT_D;
                float v1 = (mk.y ? -1e9f : acc[mt][nt][half * 2 + 1]) * INV_SQRT_D;
                *(float2*)(sbase + q * LL + col) = make_float2(v0, v1);
                acc[mt][nt][half * 2] = v0;
                acc[mt][nt][half * 2 + 1] = v1;
            }
        }
    }

    // Column stats over this block's 128 q rows (softmax is over the q axis).
    float* smax = (float*)sm;          // [4 wm][128 col]
    float* ssum = ((float*)sm) + 512;  // [4 wm][128 col]
    __syncthreads();

    // Phase A: per-column max (in-thread 4 -> butterfly over g -> smem over wm)
#pragma unroll
    for (int nt = 0; nt < 8; ++nt)
#pragma unroll
        for (int e = 0; e < 2; ++e) {
            float m = fmaxf(fmaxf(acc[0][nt][e], acc[0][nt][2 + e]),
                            fmaxf(acc[1][nt][e], acc[1][nt][2 + e]));
            m = fmaxf(m, __shfl_xor_sync(0xffffffffu, m, 16));
            m = fmaxf(m, __shfl_xor_sync(0xffffffffu, m, 8));
            m = fmaxf(m, __shfl_xor_sync(0xffffffffu, m, 4));
            if (g == 0) smax[wm * 128 + wn * 64 + nt * 8 + t * 2 + e] = m;
        }
    __syncthreads();
    float Mcol[8][2];
#pragma unroll
    for (int nt = 0; nt < 8; ++nt)
#pragma unroll
        for (int e = 0; e < 2; ++e) {
            int col = wn * 64 + nt * 8 + t * 2 + e;
            Mcol[nt][e] = fmaxf(fmaxf(smax[col], smax[128 + col]),
                                fmaxf(smax[256 + col], smax[384 + col]));
        }
    // Phase B: per-column sum of exp(v - M)
#pragma unroll
    for (int nt = 0; nt < 8; ++nt)
#pragma unroll
        for (int e = 0; e < 2; ++e) {
            float Mv = Mcol[nt][e];
            float z = __expf(acc[0][nt][e] - Mv) + __expf(acc[0][nt][2 + e] - Mv)
                    + __expf(acc[1][nt][e] - Mv) + __expf(acc[1][nt][2 + e] - Mv);
            z += __shfl_xor_sync(0xffffffffu, z, 16);
            z += __shfl_xor_sync(0xffffffffu, z, 8);
            z += __shfl_xor_sync(0xffffffffu, z, 4);
            if (g == 0) ssum[wm * 128 + wn * 64 + nt * 8 + t * 2 + e] = z;
        }
    __syncthreads();
    // One thread per column writes the block partial.
    if (wm == 0 && g == 0) {
#pragma unroll
        for (int nt = 0; nt < 8; ++nt)
#pragma unroll
            for (int e = 0; e < 2; ++e) {
                int col = wn * 64 + nt * 8 + t * 2 + e;
                float z = ssum[col] + ssum[128 + col] + ssum[256 + col] + ssum[384 + col];
                int gidx = ((blockIdx.y * HB + n) * LL) + kc0 + col;
                g_pmax[gidx] = Mcol[nt][e];
                g_psum[gidx] = z;
            }
    }
}

// ---------------------------------------------------------------------------
// K3: combine 4 q-block partials -> column M and 1/Z. grid 256, block 256.
// ---------------------------------------------------------------------------
__global__ __launch_bounds__(256) void k_colstats() {
    int idx = blockIdx.x * 256 + threadIdx.x;   // (n<<9)|k, 65536 total
    float m0 = g_pmax[idx];
    float m1 = g_pmax[65536 + idx];
    float m2 = g_pmax[131072 + idx];
    float m3 = g_pmax[196608 + idx];
    float M = fmaxf(fmaxf(m0, m1), fmaxf(m2, m3));
    float Z = g_psum[idx] * __expf(m0 - M)
            + g_psum[65536 + idx] * __expf(m1 - M)
            + g_psum[131072 + idx] * __expf(m2 - M)
            + g_psum[196608 + idx] * __expf(m3 - M);
    g_M[idx] = M;
    g_inv[idx] = 1.0f / Z;
}

// ---------------------------------------------------------------------------
// K4: AV with fused softmax apply on A. grid (1, 4, 128), block 256.
// ---------------------------------------------------------------------------
__global__ __launch_bounds__(256) void k_av() {
    extern __shared__ char sm[];
    uint32_t smb = smem_u32(sm);
    int tid = threadIdx.x, wid = tid >> 5, lane = tid & 31;
    int wm = wid & 3, wn = wid >> 2, g = lane >> 2, t = lane & 3;
    int n = blockIdx.z;
    int q0 = blockIdx.y * 128;

    float acc[2][8][4] = {};
    gemm_main<true>(sm, smb, g_S + (n * LL + q0) * LL, LL,
                    g_Vt + n * (DD * LL), LL, 16,
                    tid, wm, wn, g, t, g_M + n * LL, g_inv + n * LL, acc);

    float* abase = g_ATT + n * (LL * DD);
#pragma unroll
    for (int mt = 0; mt < 2; ++mt) {
#pragma unroll
        for (int nt = 0; nt < 8; ++nt) {
            int col = wn * 64 + nt * 8 + t * 2;
#pragma unroll
            for (int half = 0; half < 2; ++half) {
                int q = q0 + wm * 32 + mt * 16 + g + half * 8;
                *(float2*)(abase + q * DD + col) =
                    make_float2(acc[mt][nt][half * 2], acc[mt][nt][half * 2 + 1]);
            }
        }
    }
}

// ---------------------------------------------------------------------------
// K5: output projection. grid (1, 64), block 256.
// ---------------------------------------------------------------------------
__global__ __launch_bounds__(256) void k_out(const float* __restrict__ Wo,
                                             const float* __restrict__ bo,
                                             float* __restrict__ out) {
    extern __shared__ char sm[];
    uint32_t smb = smem_u32(sm);
    int tid = threadIdx.x, wid = tid >> 5, lane = tid & 31;
    int wm = wid & 3, wn = wid >> 2, g = lane >> 2, t = lane & 3;
    int m0 = blockIdx.y * 128;

    float acc[2][8][4] = {};
    gemm_main<false>(sm, smb, g_ATT + m0 * HD, HD, Wo, HD, 32,
                     tid, wm, wn, g, t, nullptr, nullptr, acc);

#pragma unroll
    for (int mt = 0; mt < 2; ++mt) {
#pragma unroll
        for (int nt = 0; nt < 8; ++nt) {
            int col = wn * 64 + nt * 8 + t * 2;
            float b0 = bo[col], b1 = bo[col + 1];
#pragma unroll
            for (int half = 0; half < 2; ++half) {
                int m = m0 + wm * 32 + mt * 16 + g + half * 8;
                *(float2*)(out + m * DD + col) =
                    make_float2(acc[mt][nt][half * 2] + b0,
                                acc[mt][nt][half * 2 + 1] + b1);
            }
        }
    }
}

// ---------------------------------------------------------------------------
extern "C" void kernel_launch(void* const* d_in, const int* in_sizes, int n_in,
                              void* d_out, int out_size) {
    const float* x  = (const float*)d_in[0];
    const float* Wq = (const float*)d_in[1];
    const float* bq = (const float*)d_in[2];
    const float* Wk = (const float*)d_in[3];
    const float* bk = (const float*)d_in[4];
    const float* Wv = (const float*)d_in[5];
    const float* bv = (const float*)d_in[6];
    const float* Wo = (const float*)d_in[7];
    const float* bo = (const float*)d_in[8];
    const int*   mask = (const int*)d_in[9];
    float* out = (float*)d_out;

    cudaFuncSetAttribute(k_qkv,    cudaFuncAttributeMaxDynamicSharedMemorySize, SMEM_BYTES);
    cudaFuncSetAttribute(k_scores, cudaFuncAttributeMaxDynamicSharedMemorySize, SMEM_BYTES);
    cudaFuncSetAttribute(k_av,     cudaFuncAttributeMaxDynamicSharedMemorySize, SMEM_BYTES);
    cudaFuncSetAttribute(k_out,    cudaFuncAttributeMaxDynamicSharedMemorySize, SMEM_BYTES);

    k_qkv<<<dim3(8, 64, 3), 256, SMEM_BYTES>>>(x, Wq, bq, Wk, bk, Wv, bv);
    k_scores<<<dim3(4, 4, 128), 256, SMEM_BYTES>>>(mask);
    k_colstats<<<256, 256>>>();
    k_av<<<dim3(1, 4, 128), 256, SMEM_BYTES>>>();
    k_out<<<dim3(1, 64), 256, SMEM_BYTES>>>(Wo, bo, out);
}

// round 14
// speedup vs baseline: 1.5197x; 1.5197x over previous
#include <cuda_runtime.h>
#include <cstdint>
#include <math.h>

// Problem constants
#define LL 512
#define DD 128
#define HB 128          // H*B
#define MM 8192         // B*L
#define HD 1024
#define INV_SQRT_D 0.08838834764831843f

// Scratch (device globals; allocation is forbidden)
__device__ __align__(128) float g_Q[HB * LL * DD];
__device__ __align__(128) float g_K[HB * LL * DD];
__device__ __align__(128) float g_Vt[HB * DD * LL];    // V transposed: [n][d][l]
__device__ __align__(128) float g_S[HB * LL * LL];     // raw masked+scaled scores
__device__ __align__(128) float g_ATT[HB * LL * DD];   // flat view == (B,L,H*D)
// Query-axis softmax stats: partial per 128-q block, then combined
__device__ __align__(128) float g_pmax[4 * HB * LL];
__device__ __align__(128) float g_psum[4 * HB * LL];
__device__ __align__(128) float g_M[HB * LL];
__device__ __align__(128) float g_inv[HB * LL];

// ---------------------------------------------------------------------------
// Tiling: block 128x128, warps 4(m) x 2(n), warp tile 32x64, K chunk 32.
// ROWPAD=40: row stride ≡ 8 banks, so warp-wide float2 reads (bank = 8g+2t)
// hit 16 distinct even banks per half-warp phase — conflict-free LDS.64.
// ---------------------------------------------------------------------------
#define KC 32
#define ROWPAD 40
#define TILE_B (128 * ROWPAD * 4)      // 20480 bytes per tile buffer
#define SMEM_BYTES (4 * TILE_B)        // A0,A1,B0,B1 = 81920

__device__ __forceinline__ uint32_t smem_u32(const void* p) {
    uint32_t a;
    asm("{ .reg .u64 t; cvta.to.shared.u64 t, %1; cvt.u32.u64 %0, t; }" : "=r"(a) : "l"(p));
    return a;
}
__device__ __forceinline__ void cp16(uint32_t saddr, const void* g) {
    asm volatile("cp.async.cg.shared.global [%0], [%1], 16;" :: "r"(saddr), "l"(g));
}
#define CP_COMMIT() asm volatile("cp.async.commit_group;" ::: "memory")
#define CP_WAIT(N)  asm volatile("cp.async.wait_group %0;" :: "n"(N) : "memory")

// Split two fp32 values (adjacent k) into packed bf16x2 hi (truncation) and
// bf16x2 lo (rounded residual). hi+lo covers ~17 mantissa bits per element.
__device__ __forceinline__ void split_bf16(float v0, float v1, uint32_t& hi, uint32_t& lo) {
    uint32_t u0 = __float_as_uint(v0);
    uint32_t u1 = __float_as_uint(v1);
    asm("prmt.b32 %0, %1, %2, 0x7632;" : "=r"(hi) : "r"(u0), "r"(u1));
    float r0 = v0 - __uint_as_float(u0 & 0xffff0000u);
    float r1 = v1 - __uint_as_float(u1 & 0xffff0000u);
    asm("cvt.rn.bf16x2.f32 %0, %1, %2;" : "=r"(lo) : "f"(r1), "f"(r0));
}

__device__ __forceinline__ void mma16(float acc[4],
                                      uint32_t a0, uint32_t a1, uint32_t a2, uint32_t a3,
                                      uint32_t b0, uint32_t b1) {
    asm volatile(
        "mma.sync.aligned.m16n8k16.row.col.f32.bf16.bf16.f32 "
        "{%0,%1,%2,%3}, {%4,%5,%6,%7}, {%8,%9}, {%0,%1,%2,%3};"
        : "+f"(acc[0]), "+f"(acc[1]), "+f"(acc[2]), "+f"(acc[3])
        : "r"(a0), "r"(a1), "r"(a2), "r"(a3), "r"(b0), "r"(b1));
}

__device__ __forceinline__ void load_async(uint32_t sbase, const float* __restrict__ src,
                                           int ld, int tid) {
#pragma unroll
    for (int i = 0; i < 4; ++i) {
        int idx = tid + i * 256;
        int row = idx >> 3;
        int c4 = idx & 7;
        cp16(sbase + (row * ROWPAD + c4 * 4) * 4, src + row * ld + c4 * 4);
    }
}

// One K=32 chunk — bf16 hi/lo split on m16n8k16, 3 terms (AhBh + AhBl + AlBh).
// Half the MMAs / splits / LDS of the tf32 path; float2 reads conflict-free
// with ROWPAD=40.
// EXP: A element -> exp(a - M[k]) * inv[k] before split (fused softmax apply).
template<bool EXP>
__device__ __forceinline__ void compute_chunk(const float (*As)[ROWPAD],
                                              const float (*Bs)[ROWPAD],
                                              int wm, int wn, int g, int t,
                                              const float* __restrict__ Mrow,
                                              const float* __restrict__ Irow,
                                              float acc[2][8][4]) {
#pragma unroll
    for (int ks = 0; ks < 2; ++ks) {
        int k0 = ks * 16 + 2 * t;   // even k of first pair (k8 group 0)
        int k1 = k0 + 8;            // even k of second pair (k8 group 1)
        float M0a = 0.f, M0b = 0.f, M1a = 0.f, M1b = 0.f;
        float I0a = 0.f, I0b = 0.f, I1a = 0.f, I1b = 0.f;
        if (EXP) {
            float2 m0 = *(const float2*)&Mrow[k0];
            float2 i0 = *(const float2*)&Irow[k0];
            float2 m1 = *(const float2*)&Mrow[k1];
            float2 i1 = *(const float2*)&Irow[k1];
            M0a = m0.x; M0b = m0.y; I0a = i0.x; I0b = i0.y;
            M1a = m1.x; M1b = m1.y; I1a = i1.x; I1b = i1.y;
        }
        uint32_t ah[2][4], al[2][4];
#pragma unroll
        for (int mt = 0; mt < 2; ++mt) {
            int r = wm * 32 + mt * 16;
            float2 v00 = *(const float2*)&As[r + g][k0];
            float2 v10 = *(const float2*)&As[r + g + 8][k0];
            float2 v01 = *(const float2*)&As[r + g][k1];
            float2 v11 = *(const float2*)&As[r + g + 8][k1];
            if (EXP) {
                v00.x = __expf(v00.x - M0a) * I0a; v00.y = __expf(v00.y - M0b) * I0b;
                v10.x = __expf(v10.x - M0a) * I0a; v10.y = __expf(v10.y - M0b) * I0b;
                v01.x = __expf(v01.x - M1a) * I1a; v01.y = __expf(v01.y - M1b) * I1b;
                v11.x = __expf(v11.x - M1a) * I1a; v11.y = __expf(v11.y - M1b) * I1b;
            }
            split_bf16(v00.x, v00.y, ah[mt][0], al[mt][0]);
            split_bf16(v10.x, v10.y, ah[mt][1], al[mt][1]);
            split_bf16(v01.x, v01.y, ah[mt][2], al[mt][2]);
            split_bf16(v11.x, v11.y, ah[mt][3], al[mt][3]);
        }
#pragma unroll
        for (int nt = 0; nt < 8; ++nt) {
            int c = wn * 64 + nt * 8;
            float2 w0 = *(const float2*)&Bs[c + g][k0];
            float2 w1 = *(const float2*)&Bs[c + g][k1];
            uint32_t bh0, bl0, bh1, bl1;
            split_bf16(w0.x, w0.y, bh0, bl0);
            split_bf16(w1.x, w1.y, bh1, bl1);
            // hh
            mma16(acc[0][nt], ah[0][0], ah[0][1], ah[0][2], ah[0][3], bh0, bh1);
            mma16(acc[1][nt], ah[1][0], ah[1][1], ah[1][2], ah[1][3], bh0, bh1);
            // hl
            mma16(acc[0][nt], ah[0][0], ah[0][1], ah[0][2], ah[0][3], bl0, bl1);
            mma16(acc[1][nt], ah[1][0], ah[1][1], ah[1][2], ah[1][3], bl0, bl1);
            // lh
            mma16(acc[0][nt], al[0][0], al[0][1], al[0][2], al[0][3], bh0, bh1);
            mma16(acc[1][nt], al[1][0], al[1][1], al[1][2], al[1][3], bh0, bh1);
        }
    }
}

// Full main loop: nc K-chunks, 2-stage cp.async pipeline (measured best).
template<bool EXP>
__device__ __forceinline__ void gemm_main(char* sm, uint32_t smb,
                                          const float* __restrict__ A, int lda,
                                          const float* __restrict__ B, int ldb,
                                          int nc, int tid, int wm, int wn, int g, int t,
                                          const float* __restrict__ Mb,
                                          const float* __restrict__ Ib,
                                          float acc[2][8][4]) {
    load_async(smb, A, lda, tid);
    load_async(smb + 2 * TILE_B, B, ldb, tid);
    CP_COMMIT();
#pragma unroll 1
    for (int c = 0; c < nc; ++c) {
        if (c + 1 < nc) {
            int nb = (c + 1) & 1;
            load_async(smb + nb * TILE_B, A + (c + 1) * KC, lda, tid);
            load_async(smb + (2 + nb) * TILE_B, B + (c + 1) * KC, ldb, tid);
            CP_COMMIT();
            CP_WAIT(1);
        } else {
            CP_WAIT(0);
        }
        __syncthreads();
        int cb = c & 1;
        compute_chunk<EXP>((const float(*)[ROWPAD])(sm + cb * TILE_B),
                           (const float(*)[ROWPAD])(sm + (2 + cb) * TILE_B),
                           wm, wn, g, t,
                           EXP ? Mb + c * KC : (const float*)nullptr,
                           EXP ? Ib + c * KC : (const float*)nullptr,
                           acc);
        __syncthreads();
    }
}

// ---------------------------------------------------------------------------
// K1: QKV projection. grid (8, 64, 3), block 256.
// ---------------------------------------------------------------------------
__global__ __launch_bounds__(256) void k_qkv(
    const float* __restrict__ x,
    const float* __restrict__ Wq, const float* __restrict__ bq,
    const float* __restrict__ Wk, const float* __restrict__ bk,
    const float* __restrict__ Wv, const float* __restrict__ bv) {
    extern __shared__ char sm[];
    uint32_t smb = smem_u32(sm);
    int tid = threadIdx.x, wid = tid >> 5, lane = tid & 31;
    int wm = wid & 3, wn = wid >> 2, g = lane >> 2, t = lane & 3;
    int sel = blockIdx.z;
    int e0 = blockIdx.x * 128;
    int m0 = blockIdx.y * 128;
    const float* W = (sel == 0) ? Wq : (sel == 1) ? Wk : Wv;
    const float* bias = (sel == 0) ? bq : (sel == 1) ? bk : bv;

    float acc[2][8][4] = {};
    gemm_main<false>(sm, smb, x + m0 * DD, DD, W + e0 * DD, DD, 4,
                     tid, wm, wn, g, t, nullptr, nullptr, acc);

    int h = e0 >> 7;
#pragma unroll
    for (int mt = 0; mt < 2; ++mt) {
#pragma unroll
        for (int nt = 0; nt < 8; ++nt) {
            int col = wn * 64 + nt * 8 + t * 2;
            float bi0 = bias[e0 + col], bi1 = bias[e0 + col + 1];
#pragma unroll
            for (int half = 0; half < 2; ++half) {
                int row = wm * 32 + mt * 16 + g + half * 8;
                int m = m0 + row;
                int b = m >> 9, l = m & 511;
                int n = (h << 4) + b;
                float v0 = acc[mt][nt][half * 2] + bi0;
                float v1 = acc[mt][nt][half * 2 + 1] + bi1;
                if (sel < 2) {
                    float* dst = ((sel == 0) ? g_Q : g_K) + (n * LL + l) * DD + col;
                    *(float2*)dst = make_float2(v0, v1);
                } else {
                    float* dst = g_Vt + n * (DD * LL) + l;
                    dst[col * LL] = v0;
                    dst[(col + 1) * LL] = v1;
                }
            }
        }
    }
}

// ---------------------------------------------------------------------------
// K2: scores + per-block column softmax partials. grid (4, 4, 128), block 256.
// ---------------------------------------------------------------------------
__global__ __launch_bounds__(256) void k_scores(const int* __restrict__ mask) {
    extern __shared__ char sm[];
    uint32_t smb = smem_u32(sm);
    int tid = threadIdx.x, wid = tid >> 5, lane = tid & 31;
    int wm = wid & 3, wn = wid >> 2, g = lane >> 2, t = lane & 3;
    int n = blockIdx.z;
    int kc0 = blockIdx.x * 128;
    int q0 = blockIdx.y * 128;

    float acc[2][8][4] = {};
    gemm_main<false>(sm, smb, g_Q + (n * LL + q0) * DD, DD,
                     g_K + (n * LL + kc0) * DD, DD, 4,
                     tid, wm, wn, g, t, nullptr, nullptr, acc);

    // Mask + scale into acc; store raw S.
    const int* mbase = mask + (n & 15) * (LL * LL);
    float* sbase = g_S + n * (LL * LL);
#pragma unroll
    for (int mt = 0; mt < 2; ++mt) {
#pragma unroll
        for (int nt = 0; nt < 8; ++nt) {
            int col = kc0 + wn * 64 + nt * 8 + t * 2;
#pragma unroll
            for (int half = 0; half < 2; ++half) {
                int q = q0 + wm * 32 + mt * 16 + g + half * 8;
                int2 mk = *(const int2*)(mbase + q * LL + col);
                float v0 = (mk.x ? -1e9f : acc[mt][nt][half * 2]) * INV_SQRT_D;
                float v1 = (mk.y ? -1e9f : acc[mt][nt][half * 2 + 1]) * INV_SQRT_D;
                *(float2*)(sbase + q * LL + col) = make_float2(v0, v1);
                acc[mt][nt][half * 2] = v0;
                acc[mt][nt][half * 2 + 1] = v1;
            }
        }
    }

    // Column stats over this block's 128 q rows (softmax is over the q axis).
    float* smax = (float*)sm;          // [4 wm][128 col]
    float* ssum = ((float*)sm) + 512;  // [4 wm][128 col]
    __syncthreads();

    // Phase A: per-column max (in-thread 4 -> butterfly over g -> smem over wm)
#pragma unroll
    for (int nt = 0; nt < 8; ++nt)
#pragma unroll
        for (int e = 0; e < 2; ++e) {
            float m = fmaxf(fmaxf(acc[0][nt][e], acc[0][nt][2 + e]),
                            fmaxf(acc[1][nt][e], acc[1][nt][2 + e]));
            m = fmaxf(m, __shfl_xor_sync(0xffffffffu, m, 16));
            m = fmaxf(m, __shfl_xor_sync(0xffffffffu, m, 8));
            m = fmaxf(m, __shfl_xor_sync(0xffffffffu, m, 4));
            if (g == 0) smax[wm * 128 + wn * 64 + nt * 8 + t * 2 + e] = m;
        }
    __syncthreads();
    float Mcol[8][2];
#pragma unroll
    for (int nt = 0; nt < 8; ++nt)
#pragma unroll
        for (int e = 0; e < 2; ++e) {
            int col = wn * 64 + nt * 8 + t * 2 + e;
            Mcol[nt][e] = fmaxf(fmaxf(smax[col], smax[128 + col]),
                                fmaxf(smax[256 + col], smax[384 + col]));
        }
    // Phase B: per-column sum of exp(v - M)
#pragma unroll
    for (int nt = 0; nt < 8; ++nt)
#pragma unroll
        for (int e = 0; e < 2; ++e) {
            float Mv = Mcol[nt][e];
            float z = __expf(acc[0][nt][e] - Mv) + __expf(acc[0][nt][2 + e] - Mv)
                    + __expf(acc[1][nt][e] - Mv) + __expf(acc[1][nt][2 + e] - Mv);
            z += __shfl_xor_sync(0xffffffffu, z, 16);
            z += __shfl_xor_sync(0xffffffffu, z, 8);
            z += __shfl_xor_sync(0xffffffffu, z, 4);
            if (g == 0) ssum[wm * 128 + wn * 64 + nt * 8 + t * 2 + e] = z;
        }
    __syncthreads();
    // One thread per column writes the block partial.
    if (wm == 0 && g == 0) {
#pragma unroll
        for (int nt = 0; nt < 8; ++nt)
#pragma unroll
            for (int e = 0; e < 2; ++e) {
                int col = wn * 64 + nt * 8 + t * 2 + e;
                float z = ssum[col] + ssum[128 + col] + ssum[256 + col] + ssum[384 + col];
                int gidx = ((blockIdx.y * HB + n) * LL) + kc0 + col;
                g_pmax[gidx] = Mcol[nt][e];
                g_psum[gidx] = z;
            }
    }
}

// ---------------------------------------------------------------------------
// K3: combine 4 q-block partials -> column M and 1/Z. grid 256, block 256.
// ---------------------------------------------------------------------------
__global__ __launch_bounds__(256) void k_colstats() {
    int idx = blockIdx.x * 256 + threadIdx.x;   // (n<<9)|k, 65536 total
    float m0 = g_pmax[idx];
    float m1 = g_pmax[65536 + idx];
    float m2 = g_pmax[131072 + idx];
    float m3 = g_pmax[196608 + idx];
    float M = fmaxf(fmaxf(m0, m1), fmaxf(m2, m3));
    float Z = g_psum[idx] * __expf(m0 - M)
            + g_psum[65536 + idx] * __expf(m1 - M)
            + g_psum[131072 + idx] * __expf(m2 - M)
            + g_psum[196608 + idx] * __expf(m3 - M);
    g_M[idx] = M;
    g_inv[idx] = 1.0f / Z;
}

// ---------------------------------------------------------------------------
// K4: AV with fused softmax apply on A. grid (1, 4, 128), block 256.
// ---------------------------------------------------------------------------
__global__ __launch_bounds__(256) void k_av() {
    extern __shared__ char sm[];
    uint32_t smb = smem_u32(sm);
    int tid = threadIdx.x, wid = tid >> 5, lane = tid & 31;
    int wm = wid & 3, wn = wid >> 2, g = lane >> 2, t = lane & 3;
    int n = blockIdx.z;
    int q0 = blockIdx.y * 128;

    float acc[2][8][4] = {};
    gemm_main<true>(sm, smb, g_S + (n * LL + q0) * LL, LL,
                    g_Vt + n * (DD * LL), LL, 16,
                    tid, wm, wn, g, t, g_M + n * LL, g_inv + n * LL, acc);

    float* abase = g_ATT + n * (LL * DD);
#pragma unroll
    for (int mt = 0; mt < 2; ++mt) {
#pragma unroll
        for (int nt = 0; nt < 8; ++nt) {
            int col = wn * 64 + nt * 8 + t * 2;
#pragma unroll
            for (int half = 0; half < 2; ++half) {
                int q = q0 + wm * 32 + mt * 16 + g + half * 8;
                *(float2*)(abase + q * DD + col) =
                    make_float2(acc[mt][nt][half * 2], acc[mt][nt][half * 2 + 1]);
            }
        }
    }
}

// ---------------------------------------------------------------------------
// K5: output projection. grid (1, 64), block 256.
// ---------------------------------------------------------------------------
__global__ __launch_bounds__(256) void k_out(const float* __restrict__ Wo,
                                             const float* __restrict__ bo,
                                             float* __restrict__ out) {
    extern __shared__ char sm[];
    uint32_t smb = smem_u32(sm);
    int tid = threadIdx.x, wid = tid >> 5, lane = tid & 31;
    int wm = wid & 3, wn = wid >> 2, g = lane >> 2, t = lane & 3;
    int m0 = blockIdx.y * 128;

    float acc[2][8][4] = {};
    gemm_main<false>(sm, smb, g_ATT + m0 * HD, HD, Wo, HD, 32,
                     tid, wm, wn, g, t, nullptr, nullptr, acc);

#pragma unroll
    for (int mt = 0; mt < 2; ++mt) {
#pragma unroll
        for (int nt = 0; nt < 8; ++nt) {
            int col = wn * 64 + nt * 8 + t * 2;
            float b0 = bo[col], b1 = bo[col + 1];
#pragma unroll
            for (int half = 0; half < 2; ++half) {
                int m = m0 + wm * 32 + mt * 16 + g + half * 8;
                *(float2*)(out + m * DD + col) =
                    make_float2(acc[mt][nt][half * 2] + b0,
                                acc[mt][nt][half * 2 + 1] + b1);
            }
        }
    }
}

// ---------------------------------------------------------------------------
extern "C" void kernel_launch(void* const* d_in, const int* in_sizes, int n_in,
                              void* d_out, int out_size) {
    const float* x  = (const float*)d_in[0];
    const float* Wq = (const float*)d_in[1];
    const float* bq = (const float*)d_in[2];
    const float* Wk = (const float*)d_in[3];
    const float* bk = (const float*)d_in[4];
    const float* Wv = (const float*)d_in[5];
    const float* bv = (const float*)d_in[6];
    const float* Wo = (const float*)d_in[7];
    const float* bo = (const float*)d_in[8];
    const int*   mask = (const int*)d_in[9];
    float* out = (float*)d_out;

    cudaFuncSetAttribute(k_qkv,    cudaFuncAttributeMaxDynamicSharedMemorySize, SMEM_BYTES);
    cudaFuncSetAttribute(k_scores, cudaFuncAttributeMaxDynamicSharedMemorySize, SMEM_BYTES);
    cudaFuncSetAttribute(k_av,     cudaFuncAttributeMaxDynamicSharedMemorySize, SMEM_BYTES);
    cudaFuncSetAttribute(k_out,    cudaFuncAttributeMaxDynamicSharedMemorySize, SMEM_BYTES);

    k_qkv<<<dim3(8, 64, 3), 256, SMEM_BYTES>>>(x, Wq, bq, Wk, bk, Wv, bv);
    k_scores<<<dim3(4, 4, 128), 256, SMEM_BYTES>>>(mask);
    k_colstats<<<256, 256>>>();
    k_av<<<dim3(1, 4, 128), 256, SMEM_BYTES>>>();
    k_out<<<dim3(1, 64), 256, SMEM_BYTES>>>(Wo, bo, out);
}